// round 6
// baseline (speedup 1.0000x reference)
#include <cuda_runtime.h>
#include <cstdint>

// ---------------------------------------------------------------------------
// Cross-modal attention, aq=1, softmax=1, sigmoid=0.
// B=16, N=4096, Kq=64, C=1024, H=8, d=128. Output (16,64,1024) fp32.
//
//   1) q    = aud @ Wq^T                  (1024 x 1024 x 1024)  NT   [tf32 mma]
//   2) qt_bh = Q_bh @ Wk_h                (64 x 1024 x 128) x128 NN  [fp32]
//   3) sc_b  = qt_b @ img_b^T * scale     (512 x 4096 x 1024) x16 NT [tf32 mma]
//   4) softmax rows of sc (8192 rows x 4096)
//   5) t_b   = sc_b @ img_b               (512 x 1024 x 4096) x16 NN [tf32 mma]
//   6) out_bh = t_bh @ Wv_h^T             (64 x 128 x 1024) x128 NT  [fp32]
//
// R6: tf32 GEMM gets register-prefetch double buffering (dynamic smem),
//     one __syncthreads per k-iter, global loads overlapped with compute.
// ---------------------------------------------------------------------------

__device__ __align__(16) float g_q[16 * 64 * 1024];        //   4 MB
__device__ __align__(16) float g_qt[16 * 8 * 64 * 1024];   //  32 MB
__device__ __align__(16) float g_sc[16 * 512 * 4096];      // 128 MB
__device__ __align__(16) float g_t[16 * 8 * 64 * 1024];    //  32 MB

__device__ __forceinline__ uint32_t f2tf32(float x) {
    uint32_t r;
    asm("cvt.rna.tf32.f32 %0, %1;" : "=r"(r) : "f"(x));
    return r;
}

// ======================= TF32 tensor-core GEMM =============================
// C[M,N] = alpha * A[M,K] * op(B), A row-major (lda = K-stride).
// TRANSB: B is N x K row-major (NT). else: B is K x N row-major (NN).
// Block tile 128x128x32, 8 warps (4x2), warp tile 32x64, mma m16n8k8.
// Double-buffered smem, register prefetch of next k-tile.
template <bool TRANSB>
__global__ __launch_bounds__(256)
void tf32_gemm_kernel(const float* __restrict__ Ag, const float* __restrict__ Bg,
                      float* __restrict__ Cg,
                      int K, int lda, int ldb, int ldc,
                      long aOff1, long bOff1, long cOff1, float alpha) {
    const float* A = Ag + (long)blockIdx.z * aOff1;
    const float* B = Bg + (long)blockIdx.z * bOff1;
    float* C = Cg + (long)blockIdx.z * cOff1;

    constexpr int AS_STRIDE = 36;      // 32 + 4 pad -> conflict-free frag loads
    constexpr int BS_STRIDE_NT = 36;
    constexpr int BS_STRIDE_NN = 136;  // 128 + 8 pad
    constexpr int AS_ELEMS = 128 * AS_STRIDE;
    constexpr int BS_ELEMS = TRANSB ? 128 * BS_STRIDE_NT : 32 * BS_STRIDE_NN;

    extern __shared__ uint32_t smem[];
    uint32_t* As = smem;                 // 2 buffers
    uint32_t* Bs = smem + 2 * AS_ELEMS;  // 2 buffers

    const int tid = threadIdx.x;
    const int lane = tid & 31;
    const int warp = tid >> 5;
    const int g = lane >> 2;      // group id (0..7)
    const int tg = lane & 3;      // thread in group (0..3)
    const int wm = warp >> 1;     // 0..3  -> warp row * 32
    const int wn = warp & 1;      // 0..1  -> warp col * 64
    const int m0 = blockIdx.y * 128;
    const int n0 = blockIdx.x * 128;

    // per-thread load coordinates (constant across iters)
    const int arow = tid >> 3;        // 0..31, rows arow + 32*i
    const int acol = (tid & 7) * 4;   // k within tile
    const int brow_nn = tid >> 5;     // 0..7, rows brow + 8*i (k)
    const int bcol_nn = (tid & 31) * 4;

    float acc[2][8][4] = {};
    float4 pa[4], pb[4];

    const int niter = K >> 5;  // K/32

    // ---- prologue: load k-tile 0 into regs, store to buffer 0 ----
    #pragma unroll
    for (int i = 0; i < 4; i++)
        pa[i] = *reinterpret_cast<const float4*>(
            A + (long)(m0 + arow + 32 * i) * lda + acol);
    if constexpr (TRANSB) {
        #pragma unroll
        for (int i = 0; i < 4; i++)
            pb[i] = *reinterpret_cast<const float4*>(
                B + (long)(n0 + arow + 32 * i) * ldb + acol);
    } else {
        #pragma unroll
        for (int i = 0; i < 4; i++)
            pb[i] = *reinterpret_cast<const float4*>(
                B + (long)(brow_nn + 8 * i) * ldb + n0 + bcol_nn);
    }
    #pragma unroll
    for (int i = 0; i < 4; i++) {
        uint32_t* dst = &As[(arow + 32 * i) * AS_STRIDE + acol];
        dst[0] = f2tf32(pa[i].x); dst[1] = f2tf32(pa[i].y);
        dst[2] = f2tf32(pa[i].z); dst[3] = f2tf32(pa[i].w);
    }
    if constexpr (TRANSB) {
        #pragma unroll
        for (int i = 0; i < 4; i++) {
            uint32_t* dst = &Bs[(arow + 32 * i) * BS_STRIDE_NT + acol];
            dst[0] = f2tf32(pb[i].x); dst[1] = f2tf32(pb[i].y);
            dst[2] = f2tf32(pb[i].z); dst[3] = f2tf32(pb[i].w);
        }
    } else {
        #pragma unroll
        for (int i = 0; i < 4; i++) {
            uint32_t* dst = &Bs[(brow_nn + 8 * i) * BS_STRIDE_NN + bcol_nn];
            dst[0] = f2tf32(pb[i].x); dst[1] = f2tf32(pb[i].y);
            dst[2] = f2tf32(pb[i].z); dst[3] = f2tf32(pb[i].w);
        }
    }
    __syncthreads();

    int buf = 0;
    for (int it = 0; it < niter; ++it) {
        const bool has_next = (it + 1) < niter;
        const int ktn = (it + 1) << 5;

        // ---- issue global loads for next k-tile (overlap with compute) ----
        if (has_next) {
            #pragma unroll
            for (int i = 0; i < 4; i++)
                pa[i] = *reinterpret_cast<const float4*>(
                    A + (long)(m0 + arow + 32 * i) * lda + ktn + acol);
            if constexpr (TRANSB) {
                #pragma unroll
                for (int i = 0; i < 4; i++)
                    pb[i] = *reinterpret_cast<const float4*>(
                        B + (long)(n0 + arow + 32 * i) * ldb + ktn + acol);
            } else {
                #pragma unroll
                for (int i = 0; i < 4; i++)
                    pb[i] = *reinterpret_cast<const float4*>(
                        B + (long)(ktn + brow_nn + 8 * i) * ldb + n0 + bcol_nn);
            }
        }

        // ---- compute from current buffer ----
        const uint32_t* AsB = As + buf * AS_ELEMS;
        const uint32_t* BsB = Bs + buf * BS_ELEMS;
        #pragma unroll
        for (int ks = 0; ks < 4; ks++) {
            const int k0 = ks * 8;
            uint32_t af[2][4];
            #pragma unroll
            for (int mi = 0; mi < 2; mi++) {
                int rb = wm * 32 + mi * 16;
                af[mi][0] = AsB[(rb + g) * AS_STRIDE + k0 + tg];
                af[mi][1] = AsB[(rb + g + 8) * AS_STRIDE + k0 + tg];
                af[mi][2] = AsB[(rb + g) * AS_STRIDE + k0 + tg + 4];
                af[mi][3] = AsB[(rb + g + 8) * AS_STRIDE + k0 + tg + 4];
            }
            uint32_t bf[8][2];
            #pragma unroll
            for (int ni = 0; ni < 8; ni++) {
                int nb = wn * 64 + ni * 8;
                if constexpr (TRANSB) {
                    bf[ni][0] = BsB[(nb + g) * BS_STRIDE_NT + k0 + tg];
                    bf[ni][1] = BsB[(nb + g) * BS_STRIDE_NT + k0 + tg + 4];
                } else {
                    bf[ni][0] = BsB[(k0 + tg) * BS_STRIDE_NN + nb + g];
                    bf[ni][1] = BsB[(k0 + tg + 4) * BS_STRIDE_NN + nb + g];
                }
            }
            #pragma unroll
            for (int mi = 0; mi < 2; mi++)
                #pragma unroll
                for (int ni = 0; ni < 8; ni++) {
                    float* c = acc[mi][ni];
                    asm volatile(
                        "mma.sync.aligned.m16n8k8.row.col.f32.tf32.tf32.f32 "
                        "{%0,%1,%2,%3}, {%4,%5,%6,%7}, {%8,%9}, {%0,%1,%2,%3};"
                        : "+f"(c[0]), "+f"(c[1]), "+f"(c[2]), "+f"(c[3])
                        : "r"(af[mi][0]), "r"(af[mi][1]), "r"(af[mi][2]),
                          "r"(af[mi][3]), "r"(bf[ni][0]), "r"(bf[ni][1]));
                }
        }

        // ---- cvt + store prefetched tile into other buffer ----
        if (has_next) {
            uint32_t* AsN = As + (buf ^ 1) * AS_ELEMS;
            uint32_t* BsN = Bs + (buf ^ 1) * BS_ELEMS;
            #pragma unroll
            for (int i = 0; i < 4; i++) {
                uint32_t* dst = &AsN[(arow + 32 * i) * AS_STRIDE + acol];
                dst[0] = f2tf32(pa[i].x); dst[1] = f2tf32(pa[i].y);
                dst[2] = f2tf32(pa[i].z); dst[3] = f2tf32(pa[i].w);
            }
            if constexpr (TRANSB) {
                #pragma unroll
                for (int i = 0; i < 4; i++) {
                    uint32_t* dst = &BsN[(arow + 32 * i) * BS_STRIDE_NT + acol];
                    dst[0] = f2tf32(pb[i].x); dst[1] = f2tf32(pb[i].y);
                    dst[2] = f2tf32(pb[i].z); dst[3] = f2tf32(pb[i].w);
                }
            } else {
                #pragma unroll
                for (int i = 0; i < 4; i++) {
                    uint32_t* dst = &BsN[(brow_nn + 8 * i) * BS_STRIDE_NN + bcol_nn];
                    dst[0] = f2tf32(pb[i].x); dst[1] = f2tf32(pb[i].y);
                    dst[2] = f2tf32(pb[i].z); dst[3] = f2tf32(pb[i].w);
                }
            }
        }
        __syncthreads();
        buf ^= 1;
    }

    // ---- epilogue ----
    #pragma unroll
    for (int mi = 0; mi < 2; mi++) {
        int r0 = m0 + wm * 32 + mi * 16 + g;
        #pragma unroll
        for (int ni = 0; ni < 8; ni++) {
            int col = n0 + wn * 64 + ni * 8 + tg * 2;
            float2 v0 = {alpha * acc[mi][ni][0], alpha * acc[mi][ni][1]};
            float2 v1 = {alpha * acc[mi][ni][2], alpha * acc[mi][ni][3]};
            *reinterpret_cast<float2*>(C + (long)r0 * ldc + col) = v0;
            *reinterpret_cast<float2*>(C + (long)(r0 + 8) * ldc + col) = v1;
        }
    }
}

// smem sizes for the two variants
static const int SMEM_TF32_NT = (2 * 128 * 36 + 2 * 128 * 36) * 4;   // 73728
static const int SMEM_TF32_NN = (2 * 128 * 36 + 2 * 32 * 136) * 4;   // 71680

// ======================= fp32 SGEMM (small steps) ==========================
template <int BM, int BN, int BK, int TM, int TN, bool TRANSB>
__global__ __launch_bounds__((BM / TM) * (BN / TN))
void sgemm_kernel(const float* __restrict__ Ag, const float* __restrict__ Bg,
                  float* __restrict__ Cg,
                  int M, int N, int K, int lda, int ldb, int ldc,
                  long aOff1, long aOff2, long bOff1, long bOff2,
                  long cOff1, long cOff2, int Z2, float alpha) {
    constexpr int THREADS = (BM / TM) * (BN / TN);
    const int z = blockIdx.z;
    const int z1 = z / Z2;
    const int z2 = z - z1 * Z2;
    const float* A = Ag + (long)z1 * aOff1 + (long)z2 * aOff2;
    const float* B = Bg + (long)z1 * bOff1 + (long)z2 * bOff2;
    float* C = Cg + (long)z1 * cOff1 + (long)z2 * cOff2;

    __shared__ __align__(16) float As[BK][BM];
    __shared__ __align__(16) float Bs[BK][BN];

    const int tid = threadIdx.x;
    const int m0 = blockIdx.y * BM;
    const int n0 = blockIdx.x * BN;
    const int tm0 = (tid / (BN / TN)) * TM;
    const int tn0 = (tid % (BN / TN)) * TN;

    float acc[TM][TN] = {};

    constexpr int KV = BK / 4;
    constexpr int A_PER = (BM * KV) / THREADS;

    for (int kt = 0; kt < K; kt += BK) {
        #pragma unroll
        for (int i = 0; i < A_PER; i++) {
            int idx = tid + i * THREADS;
            int row = idx / KV;
            int cv = idx - row * KV;
            float4 v = *reinterpret_cast<const float4*>(
                A + (long)(m0 + row) * lda + kt + cv * 4);
            As[cv * 4 + 0][row] = v.x;
            As[cv * 4 + 1][row] = v.y;
            As[cv * 4 + 2][row] = v.z;
            As[cv * 4 + 3][row] = v.w;
        }
        if constexpr (TRANSB) {
            constexpr int B_PER = (BN * KV) / THREADS;
            #pragma unroll
            for (int i = 0; i < B_PER; i++) {
                int idx = tid + i * THREADS;
                int row = idx / KV;
                int cv = idx - row * KV;
                float4 v = *reinterpret_cast<const float4*>(
                    B + (long)(n0 + row) * ldb + kt + cv * 4);
                Bs[cv * 4 + 0][row] = v.x;
                Bs[cv * 4 + 1][row] = v.y;
                Bs[cv * 4 + 2][row] = v.z;
                Bs[cv * 4 + 3][row] = v.w;
            }
        } else {
            constexpr int NV = BN / 4;
            constexpr int B_PER = (BK * NV) / THREADS;
            #pragma unroll
            for (int i = 0; i < B_PER; i++) {
                int idx = tid + i * THREADS;
                int row = idx / NV;
                int cv = idx - row * NV;
                float4 v = *reinterpret_cast<const float4*>(
                    B + (long)(kt + row) * ldb + n0 + cv * 4);
                *reinterpret_cast<float4*>(&Bs[row][cv * 4]) = v;
            }
        }
        __syncthreads();

        #pragma unroll
        for (int kk = 0; kk < BK; kk++) {
            float ra[TM], rb[TN];
            #pragma unroll
            for (int i = 0; i < TM / 4; i++)
                *reinterpret_cast<float4*>(&ra[i * 4]) =
                    *reinterpret_cast<const float4*>(&As[kk][tm0 + i * 4]);
            #pragma unroll
            for (int j = 0; j < TN / 4; j++)
                *reinterpret_cast<float4*>(&rb[j * 4]) =
                    *reinterpret_cast<const float4*>(&Bs[kk][tn0 + j * 4]);
            #pragma unroll
            for (int i = 0; i < TM; i++)
                #pragma unroll
                for (int j = 0; j < TN; j++)
                    acc[i][j] = fmaf(ra[i], rb[j], acc[i][j]);
        }
        __syncthreads();
    }

    #pragma unroll
    for (int i = 0; i < TM; i++) {
        #pragma unroll
        for (int j = 0; j < TN / 4; j++) {
            float4 v;
            v.x = alpha * acc[i][j * 4 + 0];
            v.y = alpha * acc[i][j * 4 + 1];
            v.z = alpha * acc[i][j * 4 + 2];
            v.w = alpha * acc[i][j * 4 + 3];
            *reinterpret_cast<float4*>(
                C + (long)(m0 + tm0 + i) * ldc + n0 + tn0 + j * 4) = v;
        }
    }
}

// ======================= softmax ===========================================
__global__ __launch_bounds__(256) void softmax4096_kernel(float* __restrict__ S) {
    float* row = S + (size_t)blockIdx.x * 4096;
    const int tid = threadIdx.x;
    __shared__ float red[8];

    float4 v[4];
    float maxv = -3.4e38f;
    #pragma unroll
    for (int i = 0; i < 4; i++) {
        v[i] = reinterpret_cast<const float4*>(row)[tid + i * 256];
        maxv = fmaxf(maxv, fmaxf(fmaxf(v[i].x, v[i].y), fmaxf(v[i].z, v[i].w)));
    }
    #pragma unroll
    for (int o = 16; o > 0; o >>= 1)
        maxv = fmaxf(maxv, __shfl_xor_sync(0xffffffffu, maxv, o));
    if ((tid & 31) == 0) red[tid >> 5] = maxv;
    __syncthreads();
    float bm = red[0];
    #pragma unroll
    for (int i = 1; i < 8; i++) bm = fmaxf(bm, red[i]);

    float sum = 0.f;
    #pragma unroll
    for (int i = 0; i < 4; i++) {
        v[i].x = __expf(v[i].x - bm);
        v[i].y = __expf(v[i].y - bm);
        v[i].z = __expf(v[i].z - bm);
        v[i].w = __expf(v[i].w - bm);
        sum += (v[i].x + v[i].y) + (v[i].z + v[i].w);
    }
    __syncthreads();
    #pragma unroll
    for (int o = 16; o > 0; o >>= 1) sum += __shfl_xor_sync(0xffffffffu, sum, o);
    if ((tid & 31) == 0) red[tid >> 5] = sum;
    __syncthreads();
    float tot = 0.f;
    #pragma unroll
    for (int i = 0; i < 8; i++) tot += red[i];
    const float inv = 1.0f / tot;
    #pragma unroll
    for (int i = 0; i < 4; i++) {
        v[i].x *= inv; v[i].y *= inv; v[i].z *= inv; v[i].w *= inv;
        reinterpret_cast<float4*>(row)[tid + i * 256] = v[i];
    }
}

extern "C" void kernel_launch(void* const* d_in, const int* in_sizes, int n_in,
                              void* d_out, int out_size) {
    const float* img = (const float*)d_in[0];  // (16,4096,1024)
    const float* aud = (const float*)d_in[1];  // (16,64,1024)
    const float* Wq = (const float*)d_in[2];   // (1024,1024)
    const float* Wk = (const float*)d_in[3];
    const float* Wv = (const float*)d_in[4];
    float* out = (float*)d_out;                // (16,64,1024)

    float *q, *qt, *sc, *t;
    cudaGetSymbolAddress((void**)&q, g_q);
    cudaGetSymbolAddress((void**)&qt, g_qt);
    cudaGetSymbolAddress((void**)&sc, g_sc);
    cudaGetSymbolAddress((void**)&t, g_t);

    // raise dynamic smem limits (idempotent; host-side, capture-safe)
    cudaFuncSetAttribute(tf32_gemm_kernel<true>,
                         cudaFuncAttributeMaxDynamicSharedMemorySize, SMEM_TF32_NT);
    cudaFuncSetAttribute(tf32_gemm_kernel<false>,
                         cudaFuncAttributeMaxDynamicSharedMemorySize, SMEM_TF32_NN);

    const float scale = 0.08838834764831845f;  // (1024/8)^-0.5

    // 1) q = aud @ Wq^T : M=1024, N=1024, K=1024  (tf32, NT)
    tf32_gemm_kernel<true><<<dim3(8, 8, 1), 256, SMEM_TF32_NT>>>(
        aud, Wq, q, 1024, 1024, 1024, 1024, 0, 0, 0, 1.0f);

    // 2) qt[b,h] = Q_bh @ Wk_h : M=64, N=1024, K=128, z = b*8+h (fp32, NN)
    sgemm_kernel<64, 64, 16, 4, 4, false><<<dim3(16, 1, 128), 256>>>(
        q, Wk, qt, 64, 1024, 128, 1024, 1024, 1024,
        65536, 128, 0, 131072, 524288, 65536, 8, 1.0f);

    // 3) sc_b = qt_b @ img_b^T * scale : M=512, N=4096, K=1024 (tf32, NT)
    tf32_gemm_kernel<true><<<dim3(32, 4, 16), 256, SMEM_TF32_NT>>>(
        qt, img, sc, 1024, 1024, 1024, 4096,
        524288, 4194304, 2097152, scale);

    // 4) softmax over the 4096-wide rows (16*512 rows)
    softmax4096_kernel<<<16 * 512, 256>>>(sc);

    // 5) t_b = P_b @ img_b : M=512, N=1024, K=4096 (tf32, NN)
    tf32_gemm_kernel<false><<<dim3(8, 4, 16), 256, SMEM_TF32_NN>>>(
        sc, img, t, 4096, 4096, 1024, 1024,
        2097152, 4194304, 524288, 1.0f);

    // 6) out[b,:,h*128:(h+1)*128] = t_bh @ Wv_h^T : M=64, N=128, K=1024 (fp32, NT)
    sgemm_kernel<64, 64, 16, 4, 4, true><<<dim3(2, 1, 128), 256>>>(
        t, Wv, out, 64, 128, 1024, 1024, 1024, 1024,
        524288, 65536, 0, 131072, 65536, 128, 8, 1.0f);
}

// round 8
// speedup vs baseline: 1.0943x; 1.0943x over previous
#include <cuda_runtime.h>
#include <cstdint>

// ---------------------------------------------------------------------------
// Cross-modal attention, aq=1, softmax=1, sigmoid=0.
// B=16, N=4096, Kq=64, C=1024, H=8, d=128. Output (16,64,1024) fp32.
//
//   1) q    = aud @ Wq^T                  (1024 x 1024 x 1024)  NT   [tf32 mma]
//   2) qt_bh = Q_bh @ Wk_h                (64 x 1024 x 128) x128 NN  [fp32]
//   3) sc_b  = qt_b @ img_b^T * scale     (512 x 4096 x 1024) x16 NT [tf32 mma]
//   4) softmax rows of sc (8192 rows x 4096)
//   5) t_b   = sc_b @ img_b               (512 x 1024 x 4096) x16 NN [tf32 mma]
//   6) out_bh = t_bh @ Wv_h^T             (64 x 128 x 1024) x128 NT  [fp32]
//
// R7/R8: single-buffer pipeline; fragment loads via ldmatrix.x4
//        (A in both variants, B in NT) to cut mainloop issue slots ~2.6x.
// ---------------------------------------------------------------------------

__device__ __align__(16) float g_q[16 * 64 * 1024];        //   4 MB
__device__ __align__(16) float g_qt[16 * 8 * 64 * 1024];   //  32 MB
__device__ __align__(16) float g_sc[16 * 512 * 4096];      // 128 MB
__device__ __align__(16) float g_t[16 * 8 * 64 * 1024];    //  32 MB

__device__ __forceinline__ uint32_t f2tf32(float x) {
    uint32_t r;
    asm("cvt.rna.tf32.f32 %0, %1;" : "=r"(r) : "f"(x));
    return r;
}

__device__ __forceinline__ void ldsm_x4(uint32_t& r0, uint32_t& r1,
                                        uint32_t& r2, uint32_t& r3,
                                        uint32_t addr) {
    asm volatile(
        "ldmatrix.sync.aligned.m8n8.x4.shared.b16 {%0,%1,%2,%3}, [%4];"
        : "=r"(r0), "=r"(r1), "=r"(r2), "=r"(r3) : "r"(addr));
}

// ======================= TF32 tensor-core GEMM =============================
// C[M,N] = alpha * A[M,K] * op(B), A row-major (lda = K-stride).
// TRANSB: B is N x K row-major (NT). else: B is K x N row-major (NN).
// Block tile 128x128x32, 8 warps (4x2), warp tile 32x64, mma m16n8k8.
template <bool TRANSB>
__global__ __launch_bounds__(256)
void tf32_gemm_kernel(const float* __restrict__ Ag, const float* __restrict__ Bg,
                      float* __restrict__ Cg,
                      int K, int lda, int ldb, int ldc,
                      long aOff1, long bOff1, long cOff1, float alpha) {
    const float* A = Ag + (long)blockIdx.z * aOff1;
    const float* B = Bg + (long)blockIdx.z * bOff1;
    float* C = Cg + (long)blockIdx.z * cOff1;

    constexpr int AS_STRIDE = 36;      // 32 + 4 pad: ldmatrix rows rotate banks
    constexpr int BS_STRIDE_NT = 36;
    constexpr int BS_STRIDE_NN = 136;  // 128 + 8 pad

    __shared__ uint32_t As[128 * AS_STRIDE];
    __shared__ uint32_t Bs[TRANSB ? 128 * BS_STRIDE_NT : 32 * BS_STRIDE_NN];

    const int tid = threadIdx.x;
    const int lane = tid & 31;
    const int warp = tid >> 5;
    const int g = lane >> 2;      // group id (0..7)
    const int tg = lane & 3;      // thread in group (0..3)
    const int wm = warp >> 1;     // 0..3  -> warp row * 32
    const int wn = warp & 1;      // 0..1  -> warp col * 64
    const int m0 = blockIdx.y * 128;
    const int n0 = blockIdx.x * 128;

    // ldmatrix per-lane addressing
    const int r8 = lane & 7;      // row within 8x8 tile
    const int quad = lane >> 3;   // which of the 4 tiles this lane addresses
    // A x4: quad0=(rows+0,k+0) quad1=(rows+8,k+0) quad2=(rows+0,k+4) quad3=(rows+8,k+4)
    const int a_row = wm * 32 + ((quad & 1) << 3) + r8;
    const int a_cadd = (quad >> 1) << 2;
    const uint32_t a_base0 =
        (uint32_t)__cvta_generic_to_shared(&As[a_row * AS_STRIDE + a_cadd]);
    const uint32_t a_base1 = a_base0 + 16 * AS_STRIDE * 4;
    // B NT x4: quad0=(rows+0,k+0) quad1=(rows+0,k+4) quad2=(rows+8,k+0) quad3=(rows+8,k+4)
    const int b_row = wn * 64 + ((quad >> 1) << 3) + r8;
    const int b_cadd = (quad & 1) << 2;
    const uint32_t b_base = TRANSB
        ? (uint32_t)__cvta_generic_to_shared(&Bs[b_row * BS_STRIDE_NT + b_cadd])
        : 0u;

    // loader coordinates
    const int arow = tid >> 3;        // 0..31 -> rows arow + 32*i
    const int acol = (tid & 7) * 4;
    const int brow_nn = tid >> 5;     // 0..7 -> k rows brow + 8*i
    const int bcol_nn = (tid & 31) * 4;

    float acc[2][8][4] = {};

    for (int kt = 0; kt < K; kt += 32) {
        // ---- load A tile 128x32 -> As[m][k] (tf32 bits) ----
        #pragma unroll
        for (int i = 0; i < 4; i++) {
            float4 v = *reinterpret_cast<const float4*>(
                A + (long)(m0 + arow + 32 * i) * lda + kt + acol);
            uint32_t* dst = &As[(arow + 32 * i) * AS_STRIDE + acol];
            dst[0] = f2tf32(v.x); dst[1] = f2tf32(v.y);
            dst[2] = f2tf32(v.z); dst[3] = f2tf32(v.w);
        }
        // ---- load B tile ----
        if constexpr (TRANSB) {
            #pragma unroll
            for (int i = 0; i < 4; i++) {
                float4 v = *reinterpret_cast<const float4*>(
                    B + (long)(n0 + arow + 32 * i) * ldb + kt + acol);
                uint32_t* dst = &Bs[(arow + 32 * i) * BS_STRIDE_NT + acol];
                dst[0] = f2tf32(v.x); dst[1] = f2tf32(v.y);
                dst[2] = f2tf32(v.z); dst[3] = f2tf32(v.w);
            }
        } else {
            #pragma unroll
            for (int i = 0; i < 4; i++) {
                float4 v = *reinterpret_cast<const float4*>(
                    B + (long)(kt + brow_nn + 8 * i) * ldb + n0 + bcol_nn);
                uint32_t* dst = &Bs[(brow_nn + 8 * i) * BS_STRIDE_NN + bcol_nn];
                dst[0] = f2tf32(v.x); dst[1] = f2tf32(v.y);
                dst[2] = f2tf32(v.z); dst[3] = f2tf32(v.w);
            }
        }
        __syncthreads();

        #pragma unroll
        for (int ks = 0; ks < 4; ks++) {
            const int k0 = ks * 8;
            const uint32_t koff = (uint32_t)k0 * 4;

            uint32_t af[2][4];
            ldsm_x4(af[0][0], af[0][1], af[0][2], af[0][3], a_base0 + koff);
            ldsm_x4(af[1][0], af[1][1], af[1][2], af[1][3], a_base1 + koff);

            uint32_t bf[8][2];
            if constexpr (TRANSB) {
                #pragma unroll
                for (int nip = 0; nip < 4; nip++) {
                    ldsm_x4(bf[2 * nip][0], bf[2 * nip][1],
                            bf[2 * nip + 1][0], bf[2 * nip + 1][1],
                            b_base + nip * (16 * BS_STRIDE_NT * 4) + koff);
                }
            } else {
                #pragma unroll
                for (int ni = 0; ni < 8; ni++) {
                    int nb = wn * 64 + ni * 8;
                    bf[ni][0] = Bs[(k0 + tg) * BS_STRIDE_NN + nb + g];
                    bf[ni][1] = Bs[(k0 + tg + 4) * BS_STRIDE_NN + nb + g];
                }
            }

            #pragma unroll
            for (int mi = 0; mi < 2; mi++)
                #pragma unroll
                for (int ni = 0; ni < 8; ni++) {
                    float* c = acc[mi][ni];
                    asm volatile(
                        "mma.sync.aligned.m16n8k8.row.col.f32.tf32.tf32.f32 "
                        "{%0,%1,%2,%3}, {%4,%5,%6,%7}, {%8,%9}, {%0,%1,%2,%3};"
                        : "+f"(c[0]), "+f"(c[1]), "+f"(c[2]), "+f"(c[3])
                        : "r"(af[mi][0]), "r"(af[mi][1]), "r"(af[mi][2]),
                          "r"(af[mi][3]), "r"(bf[ni][0]), "r"(bf[ni][1]));
                }
        }
        __syncthreads();
    }

    // ---- epilogue ----
    #pragma unroll
    for (int mi = 0; mi < 2; mi++) {
        int r0 = m0 + wm * 32 + mi * 16 + g;
        #pragma unroll
        for (int ni = 0; ni < 8; ni++) {
            int col = n0 + wn * 64 + ni * 8 + tg * 2;
            float2 v0 = {alpha * acc[mi][ni][0], alpha * acc[mi][ni][1]};
            float2 v1 = {alpha * acc[mi][ni][2], alpha * acc[mi][ni][3]};
            *reinterpret_cast<float2*>(C + (long)r0 * ldc + col) = v0;
            *reinterpret_cast<float2*>(C + (long)(r0 + 8) * ldc + col) = v1;
        }
    }
}

// ======================= fp32 SGEMM (small steps) ==========================
template <int BM, int BN, int BK, int TM, int TN, bool TRANSB>
__global__ __launch_bounds__((BM / TM) * (BN / TN))
void sgemm_kernel(const float* __restrict__ Ag, const float* __restrict__ Bg,
                  float* __restrict__ Cg,
                  int M, int N, int K, int lda, int ldb, int ldc,
                  long aOff1, long aOff2, long bOff1, long bOff2,
                  long cOff1, long cOff2, int Z2, float alpha) {
    constexpr int THREADS = (BM / TM) * (BN / TN);
    const int z = blockIdx.z;
    const int z1 = z / Z2;
    const int z2 = z - z1 * Z2;
    const float* A = Ag + (long)z1 * aOff1 + (long)z2 * aOff2;
    const float* B = Bg + (long)z1 * bOff1 + (long)z2 * bOff2;
    float* C = Cg + (long)z1 * cOff1 + (long)z2 * cOff2;

    __shared__ __align__(16) float As[BK][BM];
    __shared__ __align__(16) float Bs[BK][BN];

    const int tid = threadIdx.x;
    const int m0 = blockIdx.y * BM;
    const int n0 = blockIdx.x * BN;
    const int tm0 = (tid / (BN / TN)) * TM;
    const int tn0 = (tid % (BN / TN)) * TN;

    float acc[TM][TN] = {};

    constexpr int KV = BK / 4;
    constexpr int A_PER = (BM * KV) / THREADS;

    for (int kt = 0; kt < K; kt += BK) {
        #pragma unroll
        for (int i = 0; i < A_PER; i++) {
            int idx = tid + i * THREADS;
            int row = idx / KV;
            int cv = idx - row * KV;
            float4 v = *reinterpret_cast<const float4*>(
                A + (long)(m0 + row) * lda + kt + cv * 4);
            As[cv * 4 + 0][row] = v.x;
            As[cv * 4 + 1][row] = v.y;
            As[cv * 4 + 2][row] = v.z;
            As[cv * 4 + 3][row] = v.w;
        }
        if constexpr (TRANSB) {
            constexpr int B_PER = (BN * KV) / THREADS;
            #pragma unroll
            for (int i = 0; i < B_PER; i++) {
                int idx = tid + i * THREADS;
                int row = idx / KV;
                int cv = idx - row * KV;
                float4 v = *reinterpret_cast<const float4*>(
                    B + (long)(n0 + row) * ldb + kt + cv * 4);
                Bs[cv * 4 + 0][row] = v.x;
                Bs[cv * 4 + 1][row] = v.y;
                Bs[cv * 4 + 2][row] = v.z;
                Bs[cv * 4 + 3][row] = v.w;
            }
        } else {
            constexpr int NV = BN / 4;
            constexpr int B_PER = (BK * NV) / THREADS;
            #pragma unroll
            for (int i = 0; i < B_PER; i++) {
                int idx = tid + i * THREADS;
                int row = idx / NV;
                int cv = idx - row * NV;
                float4 v = *reinterpret_cast<const float4*>(
                    B + (long)(kt + row) * ldb + n0 + cv * 4);
                *reinterpret_cast<float4*>(&Bs[row][cv * 4]) = v;
            }
        }
        __syncthreads();

        #pragma unroll
        for (int kk = 0; kk < BK; kk++) {
            float ra[TM], rb[TN];
            #pragma unroll
            for (int i = 0; i < TM / 4; i++)
                *reinterpret_cast<float4*>(&ra[i * 4]) =
                    *reinterpret_cast<const float4*>(&As[kk][tm0 + i * 4]);
            #pragma unroll
            for (int j = 0; j < TN / 4; j++)
                *reinterpret_cast<float4*>(&rb[j * 4]) =
                    *reinterpret_cast<const float4*>(&Bs[kk][tn0 + j * 4]);
            #pragma unroll
            for (int i = 0; i < TM; i++)
                #pragma unroll
                for (int j = 0; j < TN; j++)
                    acc[i][j] = fmaf(ra[i], rb[j], acc[i][j]);
        }
        __syncthreads();
    }

    #pragma unroll
    for (int i = 0; i < TM; i++) {
        #pragma unroll
        for (int j = 0; j < TN / 4; j++) {
            float4 v;
            v.x = alpha * acc[i][j * 4 + 0];
            v.y = alpha * acc[i][j * 4 + 1];
            v.z = alpha * acc[i][j * 4 + 2];
            v.w = alpha * acc[i][j * 4 + 3];
            *reinterpret_cast<float4*>(
                C + (long)(m0 + tm0 + i) * ldc + n0 + tn0 + j * 4) = v;
        }
    }
}

// ======================= softmax ===========================================
__global__ __launch_bounds__(256) void softmax4096_kernel(float* __restrict__ S) {
    float* row = S + (size_t)blockIdx.x * 4096;
    const int tid = threadIdx.x;
    __shared__ float red[8];

    float4 v[4];
    float maxv = -3.4e38f;
    #pragma unroll
    for (int i = 0; i < 4; i++) {
        v[i] = reinterpret_cast<const float4*>(row)[tid + i * 256];
        maxv = fmaxf(maxv, fmaxf(fmaxf(v[i].x, v[i].y), fmaxf(v[i].z, v[i].w)));
    }
    #pragma unroll
    for (int o = 16; o > 0; o >>= 1)
        maxv = fmaxf(maxv, __shfl_xor_sync(0xffffffffu, maxv, o));
    if ((tid & 31) == 0) red[tid >> 5] = maxv;
    __syncthreads();
    float bm = red[0];
    #pragma unroll
    for (int i = 1; i < 8; i++) bm = fmaxf(bm, red[i]);

    float sum = 0.f;
    #pragma unroll
    for (int i = 0; i < 4; i++) {
        v[i].x = __expf(v[i].x - bm);
        v[i].y = __expf(v[i].y - bm);
        v[i].z = __expf(v[i].z - bm);
        v[i].w = __expf(v[i].w - bm);
        sum += (v[i].x + v[i].y) + (v[i].z + v[i].w);
    }
    __syncthreads();
    #pragma unroll
    for (int o = 16; o > 0; o >>= 1) sum += __shfl_xor_sync(0xffffffffu, sum, o);
    if ((tid & 31) == 0) red[tid >> 5] = sum;
    __syncthreads();
    float tot = 0.f;
    #pragma unroll
    for (int i = 0; i < 8; i++) tot += red[i];
    const float inv = 1.0f / tot;
    #pragma unroll
    for (int i = 0; i < 4; i++) {
        v[i].x *= inv; v[i].y *= inv; v[i].z *= inv; v[i].w *= inv;
        reinterpret_cast<float4*>(row)[tid + i * 256] = v[i];
    }
}

extern "C" void kernel_launch(void* const* d_in, const int* in_sizes, int n_in,
                              void* d_out, int out_size) {
    const float* img = (const float*)d_in[0];  // (16,4096,1024)
    const float* aud = (const float*)d_in[1];  // (16,64,1024)
    const float* Wq = (const float*)d_in[2];   // (1024,1024)
    const float* Wk = (const float*)d_in[3];
    const float* Wv = (const float*)d_in[4];
    float* out = (float*)d_out;                // (16,64,1024)

    float *q, *qt, *sc, *t;
    cudaGetSymbolAddress((void**)&q, g_q);
    cudaGetSymbolAddress((void**)&qt, g_qt);
    cudaGetSymbolAddress((void**)&sc, g_sc);
    cudaGetSymbolAddress((void**)&t, g_t);

    const float scale = 0.08838834764831845f;  // (1024/8)^-0.5

    // 1) q = aud @ Wq^T : M=1024, N=1024, K=1024  (tf32, NT)
    tf32_gemm_kernel<true><<<dim3(8, 8, 1), 256>>>(
        aud, Wq, q, 1024, 1024, 1024, 1024, 0, 0, 0, 1.0f);

    // 2) qt[b,h] = Q_bh @ Wk_h : M=64, N=1024, K=128, z = b*8+h (fp32, NN)
    sgemm_kernel<64, 64, 16, 4, 4, false><<<dim3(16, 1, 128), 256>>>(
        q, Wk, qt, 64, 1024, 128, 1024, 1024, 1024,
        65536, 128, 0, 131072, 524288, 65536, 8, 1.0f);

    // 3) sc_b = qt_b @ img_b^T * scale : M=512, N=4096, K=1024 (tf32, NT)
    tf32_gemm_kernel<true><<<dim3(32, 4, 16), 256>>>(
        qt, img, sc, 1024, 1024, 1024, 4096,
        524288, 4194304, 2097152, scale);

    // 4) softmax over the 4096-wide rows (16*512 rows)
    softmax4096_kernel<<<16 * 512, 256>>>(sc);

    // 5) t_b = P_b @ img_b : M=512, N=1024, K=4096 (tf32, NN)
    tf32_gemm_kernel<false><<<dim3(8, 4, 16), 256>>>(
        sc, img, t, 4096, 4096, 1024, 1024,
        2097152, 4194304, 524288, 1.0f);

    // 6) out[b,:,h*128:(h+1)*128] = t_bh @ Wv_h^T : M=64, N=128, K=1024 (fp32, NT)
    sgemm_kernel<64, 64, 16, 4, 4, true><<<dim3(2, 1, 128), 256>>>(
        t, Wv, out, 64, 128, 1024, 1024, 1024, 1024,
        524288, 65536, 0, 131072, 65536, 128, 8, 1.0f);
}